// round 10
// baseline (speedup 1.0000x reference)
#include <cuda_runtime.h>
#include <cstdint>
#include <cstddef>

#define T_DIM 256
#define B_DIM 2048
#define DIN   128
#define NQ    16
#define GN    64
#define M_TOT (T_DIM * B_DIM)

// ZX scratch padded by 4 timesteps so phase-2 prefetch needs no bounds check.
__device__ __align__(256) float g_zx[(size_t)(T_DIM + 4) * B_DIM * GN];
// per-timestep completion counters (8 producer blocks per timestep)
__device__ int g_cnt[T_DIM];

__global__ void qlstm_reset() { g_cnt[threadIdx.x] = 0; }

// ===========================================================================
// P1 machinery (R8, measured): mma.sync m16n8k16 bf16, 3xBF16 split.
// ===========================================================================
#define SROW8 20
#define WS_OFF 256
#define XS_OFF (WS_OFF + 64 * SROW8 * 8)
#define P1_SMEM (XS_OFF + 256 * SROW8 * 8)    // 51456

__device__ __forceinline__ uint2 bf16_split2(float x, float y) {
    uint32_t h, l;
    asm("cvt.rn.bf16x2.f32 %0, %1, %2;" : "=r"(h) : "f"(y), "f"(x));
    const float hx = __uint_as_float(h << 16);
    const float hy = __uint_as_float(h & 0xffff0000u);
    const float lx = x - hx, ly = y - hy;
    asm("cvt.rn.bf16x2.f32 %0, %1, %2;" : "=r"(l) : "f"(ly), "f"(lx));
    return make_uint2(h, l);
}

#define MMA_BF16(c, a0, a1, a2, a3, b0, b1) \
    asm volatile("mma.sync.aligned.m16n8k16.row.col.f32.bf16.bf16.f32 " \
        "{%0,%1,%2,%3}, {%4,%5,%6,%7}, {%8,%9}, {%0,%1,%2,%3};" \
        : "+f"((c)[0]), "+f"((c)[1]), "+f"((c)[2]), "+f"((c)[3]) \
        : "r"(a0), "r"(a1), "r"(a2), "r"(a3), "r"(b0), "r"(b1))

// ===========================================================================
// P2 machinery (R8, measured): packed f32x2 dots, poly activations, shfl scan.
// ===========================================================================
#define FMA_X2(d, a, b, c) \
    asm("fma.rn.f32x2 %0, %1, %2, %3;" : "=l"(d) : "l"(a), "l"(b), "l"(c))
#define PACK2(d, x, y) \
    asm("mov.b64 %0, {%1, %2};" : "=l"(d) : "f"(x), "f"(y))
#define UNPACK2(x, y, d) \
    asm("mov.b64 {%0, %1}, %2;" : "=f"(x), "=f"(y) : "l"(d))

#define SA1 0.25f
#define SA3 (-2.0833333e-2f)
#define SA5 (2.0833333e-3f)
#define SA7 (-2.1081349e-4f)
#define SA9 (2.1356922e-5f)
__device__ __forceinline__ float sig_poly(float q) {
    const float u = q * q;
    float p = fmaf(SA9, u, SA7);
    p = fmaf(p, u, SA5);
    p = fmaf(p, u, SA3);
    p = fmaf(p, u, SA1);
    return fmaf(p, q, 0.5f);
}
__device__ __forceinline__ float tanh_pade(float x) {
    const float u = x * x;
    const float n = fmaf(u + 105.0f, u, 945.0f);
    const float d = fmaf(fmaf(15.0f, u, 420.0f), u, 945.0f);
    return __fdividef(x * n, d);
}
__device__ __forceinline__ float scanp(float p, int n) {
    float v1 = __shfl_up_sync(0xffffffffu, p, 1, 16);
    float v2 = __shfl_up_sync(0xffffffffu, p, 2, 16);
    float v3 = __shfl_up_sync(0xffffffffu, p, 3, 16);
    float m = ((n >= 1) ? v1 : 1.0f) * ((n >= 2) ? v2 : 1.0f);
    p *= m * ((n >= 3) ? v3 : 1.0f);
    float w1 = __shfl_up_sync(0xffffffffu, p, 4, 16);
    float w2 = __shfl_up_sync(0xffffffffu, p, 8, 16);
    float w3 = __shfl_up_sync(0xffffffffu, p, 12, 16);
    float mm = ((n >= 4) ? w1 : 1.0f) * ((n >= 8) ? w2 : 1.0f);
    return p * (mm * ((n >= 12) ? w3 : 1.0f));
}

// wait until timesteps [s0, s1] are fully produced (8 blocks each)
__device__ __forceinline__ void wait_steps(int s0, int s1) {
#pragma unroll 1
    for (int s = s0; s <= s1; ++s) {
        while (*(volatile int*)&g_cnt[s] < 8) __nanosleep(128);
    }
    __threadfence();
}

// ===========================================================================
// Fused kernel. Every block produces one 256-row ZX tile (timestep pb>>3).
// Blocks 0..63 then morph into recurrence consumers: 32 elements per block,
// 2 elements per 16-lane group (interleaved chains for ILP).
// ===========================================================================
__global__ __launch_bounds__(256, 2) void qlstm_fused(
    const float* __restrict__ X,
    const float* __restrict__ W,      // [64][144]
    const float* __restrict__ Bb,
    const float* __restrict__ Th,
    float* __restrict__ out,
    const int write_final)
{
    extern __shared__ char smem[];
    const int tid = threadIdx.x;
    const int pb  = blockIdx.x;

    // ======================= P1: produce ZX tile =======================
    {
        float* bts = (float*)smem;
        uint2* Ws2 = (uint2*)(smem + WS_OFF);
        uint2* Xs2 = (uint2*)(smem + XS_OFF);

        const int lane = tid & 31, w = tid >> 5;
        const int g = lane >> 2, tig = lane & 3;
        const int rb = w * 32;
        const size_t m0 = (size_t)pb * 256;

        if (tid < 64) bts[tid] = Bb[tid] + Th[tid];

        const int sr = tid >> 3, sq = tid & 7;

        float C[2][8][4];
#pragma unroll
        for (int s = 0; s < 2; s++)
#pragma unroll
            for (int nt = 0; nt < 8; nt++)
#pragma unroll
                for (int q = 0; q < 4; q++) C[s][nt][q] = 0.0f;

        float4 xr[8], wr[2];
#pragma unroll
        for (int i = 0; i < 8; i++)
            xr[i] = *(const float4*)(X + (m0 + sr + 32 * i) * DIN + 4 * sq);
#pragma unroll
        for (int i = 0; i < 2; i++)
            wr[i] = *(const float4*)(W + (sr + 32 * i) * 144 + 4 * sq);

        for (int kc = 0; kc < 4; kc++) {
#pragma unroll
            for (int i = 0; i < 8; i++) {
                const uint2 u0 = bf16_split2(xr[i].x, xr[i].y);
                const uint2 u1 = bf16_split2(xr[i].z, xr[i].w);
                *(uint4*)&Xs2[(sr + 32 * i) * SROW8 + 2 * sq] =
                    make_uint4(u0.x, u0.y, u1.x, u1.y);
            }
#pragma unroll
            for (int i = 0; i < 2; i++) {
                const uint2 u0 = bf16_split2(wr[i].x, wr[i].y);
                const uint2 u1 = bf16_split2(wr[i].z, wr[i].w);
                *(uint4*)&Ws2[(sr + 32 * i) * SROW8 + 2 * sq] =
                    make_uint4(u0.x, u0.y, u1.x, u1.y);
            }
            __syncthreads();

            if (kc < 3) {
                const int kb = (kc + 1) * 32;
#pragma unroll
                for (int i = 0; i < 8; i++)
                    xr[i] = *(const float4*)(X + (m0 + sr + 32 * i) * DIN + kb + 4 * sq);
#pragma unroll
                for (int i = 0; i < 2; i++)
                    wr[i] = *(const float4*)(W + (sr + 32 * i) * 144 + kb + 4 * sq);
            }

#pragma unroll
            for (int ks = 0; ks < 2; ks++) {
                const int kp = ks * 8 + tig;
                const uint2 A0 = Xs2[(rb + g) * SROW8 + kp];
                const uint2 A1 = Xs2[(rb + 8 + g) * SROW8 + kp];
                const uint2 A2 = Xs2[(rb + g) * SROW8 + kp + 4];
                const uint2 A3 = Xs2[(rb + 8 + g) * SROW8 + kp + 4];
                const uint2 D0 = Xs2[(rb + 16 + g) * SROW8 + kp];
                const uint2 D1 = Xs2[(rb + 24 + g) * SROW8 + kp];
                const uint2 D2 = Xs2[(rb + 16 + g) * SROW8 + kp + 4];
                const uint2 D3 = Xs2[(rb + 24 + g) * SROW8 + kp + 4];
#pragma unroll
                for (int nt = 0; nt < 8; nt++) {
                    const uint2 B0 = Ws2[(nt * 8 + g) * SROW8 + kp];
                    const uint2 B1 = Ws2[(nt * 8 + g) * SROW8 + kp + 4];
                    MMA_BF16(C[0][nt], A0.x, A1.x, A2.x, A3.x, B0.x, B1.x);
                    MMA_BF16(C[0][nt], A0.y, A1.y, A2.y, A3.y, B0.x, B1.x);
                    MMA_BF16(C[0][nt], A0.x, A1.x, A2.x, A3.x, B0.y, B1.y);
                    MMA_BF16(C[1][nt], D0.x, D1.x, D2.x, D3.x, B0.x, B1.x);
                    MMA_BF16(C[1][nt], D0.y, D1.y, D2.y, D3.y, B0.x, B1.x);
                    MMA_BF16(C[1][nt], D0.x, D1.x, D2.x, D3.x, B0.y, B1.y);
                }
            }
            __syncthreads();
        }

        float2 bt2[8];
#pragma unroll
        for (int nt = 0; nt < 8; nt++)
            bt2[nt] = *(const float2*)&bts[nt * 8 + 2 * tig];

#pragma unroll
        for (int s = 0; s < 2; s++) {
            const size_t r0 = m0 + rb + 16 * s + g;
#pragma unroll
            for (int nt = 0; nt < 8; nt++) {
                const int col = nt * 8 + 2 * tig;
                *(float2*)&g_zx[r0 * GN + col] =
                    make_float2(C[s][nt][0] + bt2[nt].x, C[s][nt][1] + bt2[nt].y);
                *(float2*)&g_zx[(r0 + 8) * GN + col] =
                    make_float2(C[s][nt][2] + bt2[nt].x, C[s][nt][3] + bt2[nt].y);
            }
        }
    }

    __threadfence();
    __syncthreads();
    if (tid == 0) atomicAdd(&g_cnt[pb >> 3], 1);

    if (pb >= 64) return;

    // ========== P2: recurrence (blocks 0..63, 2 elements per group) ==========
    __shared__ float hs[2][2][16][16];    // [buf][j][grp][n]

    const int n   = tid & 15;
    const int grp = tid >> 4;             // 0..15

    unsigned long long Wab[16], Wcd[16];
#pragma unroll
    for (int j = 0; j < 16; j++) {
        const float w0 = W[(size_t)(0 * 16 + n) * 144 + 128 + j];
        const float w1 = W[(size_t)(1 * 16 + n) * 144 + 128 + j];
        const float w2 = W[(size_t)(2 * 16 + n) * 144 + 128 + j];
        const float w3 = W[(size_t)(3 * 16 + n) * 144 + 128 + j];
        PACK2(Wab[j], w0, w1);
        PACK2(Wcd[j], w2, w3);
    }

    float cst[2] = {0.0f, 0.0f}, hst[2] = {0.0f, 0.0f};
    hs[0][0][grp][n] = 0.0f;
    hs[0][1][grp][n] = 0.0f;
    __syncwarp();

    const size_t SS = (size_t)B_DIM * GN;
    const int e0 = pb * 32 + grp;             // j=0 element
    const int e1 = pb * 32 + 16 + grp;        // j=1 element
    const float* zp0 = g_zx + (size_t)e0 * GN + n;
    const float* zp1 = g_zx + (size_t)e1 * GN + n;
    float* outp0 = out + (size_t)e0 * NQ + n;
    float* outp1 = out + (size_t)e1 * NQ + n;

    // 2-step prefetch groups
    wait_steps(0, 1);
    float zc[2][2][4];                        // [j][s][gate]
#pragma unroll
    for (int s = 0; s < 2; s++)
#pragma unroll
        for (int g = 0; g < 4; g++) {
            zc[0][s][g] = zp0[s * SS + g * 16];
            zc[1][s][g] = zp1[s * SS + g * 16];
        }
    zp0 += 2 * SS; zp1 += 2 * SS;

    for (int tb = 0; tb < 128; ++tb) {
        if (tb < 127) wait_steps(2 * tb + 2, 2 * tb + 3);
        float zn[2][2][4];
#pragma unroll
        for (int s = 0; s < 2; s++)
#pragma unroll
            for (int g = 0; g < 4; g++) {
                zn[0][s][g] = zp0[s * SS + g * 16];
                zn[1][s][g] = zp1[s * SS + g * 16];
            }
        zp0 += 2 * SS; zp1 += 2 * SS;

#pragma unroll
        for (int s = 0; s < 2; s++) {
#pragma unroll
            for (int j = 0; j < 2; j++) {
                float hv[16];
                {
                    const float4* hp = (const float4*)hs[s][j][grp];
#pragma unroll
                    for (int q = 0; q < 4; q++) {
                        const float4 v = hp[q];
                        hv[4 * q + 0] = v.x; hv[4 * q + 1] = v.y;
                        hv[4 * q + 2] = v.z; hv[4 * q + 3] = v.w;
                    }
                }
                unsigned long long ab0, ab1, cd0, cd1;
                PACK2(ab0, zc[j][s][0], zc[j][s][1]);
                PACK2(cd0, zc[j][s][2], zc[j][s][3]);
                PACK2(ab1, 0.0f, 0.0f);
                PACK2(cd1, 0.0f, 0.0f);
#pragma unroll
                for (int k = 0; k < 8; k++) {
                    unsigned long long h20, h21;
                    PACK2(h20, hv[k], hv[k]);
                    PACK2(h21, hv[k + 8], hv[k + 8]);
                    FMA_X2(ab0, h20, Wab[k], ab0);
                    FMA_X2(cd0, h20, Wcd[k], cd0);
                    FMA_X2(ab1, h21, Wab[k + 8], ab1);
                    FMA_X2(cd1, h21, Wcd[k + 8], cd1);
                }
                float za, zb, zg, zo, t0, t1;
                UNPACK2(za, zb, ab0); UNPACK2(t0, t1, ab1);
                za += t0; zb += t1;
                UNPACK2(zg, zo, cd0); UNPACK2(t0, t1, cd1);
                zg += t0; zo += t1;

                const float q0 = scanp(__cosf(za), n);
                const float q1 = scanp(__cosf(zb), n);
                const float q2 = scanp(__cosf(zg), n);
                const float q3 = scanp(__cosf(zo), n);

                const float f  = sig_poly(q0);
                const float ii = sig_poly(q1);
                const float gg = tanh_pade(q2);
                const float oo = sig_poly(q3);
                cst[j] = fmaf(f, cst[j], ii * gg);
                hst[j] = oo * tanh_pade(cst[j]);

                hs[s ^ 1][j][grp][n] = hst[j];
            }
            outp0[0] = hst[0];
            outp1[0] = hst[1];
            outp0 += B_DIM * NQ;
            outp1 += B_DIM * NQ;
            __syncwarp();
        }
#pragma unroll
        for (int j = 0; j < 2; j++)
#pragma unroll
            for (int s = 0; s < 2; s++)
#pragma unroll
                for (int g = 0; g < 4; g++) zc[j][s][g] = zn[j][s][g];
    }

    if (write_final) {
        float* hx = out + (size_t)T_DIM * B_DIM * NQ;
        hx[(size_t)e0 * NQ + n] = hst[0];
        hx[(size_t)e1 * NQ + n] = hst[1];
        hx[(size_t)B_DIM * NQ + (size_t)e0 * NQ + n] = cst[0];
        hx[(size_t)B_DIM * NQ + (size_t)e1 * NQ + n] = cst[1];
    }
}

// ---------------------------------------------------------------------------
extern "C" void kernel_launch(void* const* d_in, const int* in_sizes, int n_in,
                              void* d_out, int out_size) {
    const float* X  = (const float*)d_in[0];
    const float* W  = (const float*)d_in[1];
    const float* Bb = (const float*)d_in[2];
    const float* Th = (const float*)d_in[3];
    float* out = (float*)d_out;

    cudaFuncSetAttribute(qlstm_fused, cudaFuncAttributeMaxDynamicSharedMemorySize,
                         P1_SMEM);

    const int need = T_DIM * B_DIM * NQ + 2 * B_DIM * NQ;
    const int wf = (out_size >= need) ? 1 : 0;

    qlstm_reset<<<1, T_DIM>>>();
    qlstm_fused<<<M_TOT / 256, 256, P1_SMEM>>>(X, W, Bb, Th, out, wf);
}

// round 11
// speedup vs baseline: 1.2268x; 1.2268x over previous
#include <cuda_runtime.h>
#include <cstdint>
#include <cstddef>

#define T_DIM 256
#define B_DIM 2048
#define DIN   128
#define NQ    16
#define GN    64
#define M_TOT (T_DIM * B_DIM)

// ZX scratch padded by 4 timesteps so phase-2 prefetch needs no bounds check.
__device__ __align__(256) float g_zx[(size_t)(T_DIM + 4) * B_DIM * GN];

// ===========================================================================
// Phase 1: mma.sync m16n8k16 bf16, 3xBF16 split (hh+lh+hl).
// 3 CTAs/SM: block = 128 rows x 64 cols, warp = 16 rows x 64 cols.
// K = 128 in 4 chunks of 32, register-prefetched.
// ===========================================================================
#define SROW8 20                              // uint2 per row
#define WS_OFF 256
#define XS_OFF (WS_OFF + 64 * SROW8 * 8)      // 10496
#define P1_SMEM (XS_OFF + 128 * SROW8 * 8)    // 30976

__device__ __forceinline__ uint2 bf16_split2(float x, float y) {
    uint32_t h, l;
    asm("cvt.rn.bf16x2.f32 %0, %1, %2;" : "=r"(h) : "f"(y), "f"(x));
    const float hx = __uint_as_float(h << 16);
    const float hy = __uint_as_float(h & 0xffff0000u);
    const float lx = x - hx, ly = y - hy;
    asm("cvt.rn.bf16x2.f32 %0, %1, %2;" : "=r"(l) : "f"(ly), "f"(lx));
    return make_uint2(h, l);
}

#define MMA_BF16(c, a0, a1, a2, a3, b0, b1) \
    asm volatile("mma.sync.aligned.m16n8k16.row.col.f32.bf16.bf16.f32 " \
        "{%0,%1,%2,%3}, {%4,%5,%6,%7}, {%8,%9}, {%0,%1,%2,%3};" \
        : "+f"((c)[0]), "+f"((c)[1]), "+f"((c)[2]), "+f"((c)[3]) \
        : "r"(a0), "r"(a1), "r"(a2), "r"(a3), "r"(b0), "r"(b1))

__global__ __launch_bounds__(256, 3) void qlstm_p1(
    const float* __restrict__ X,
    const float* __restrict__ W,      // [64][144]
    const float* __restrict__ Bb,
    const float* __restrict__ Th)
{
    extern __shared__ char smem[];
    float* bts = (float*)smem;
    uint2* Ws2 = (uint2*)(smem + WS_OFF);   // [n=64][kp], stride 20
    uint2* Xs2 = (uint2*)(smem + XS_OFF);   // [row=128][kp], stride 20

    const int tid  = threadIdx.x;
    const int lane = tid & 31, w = tid >> 5;
    const int g = lane >> 2, tig = lane & 3;
    const int rb = w * 16;
    const size_t m0 = (size_t)blockIdx.x * 128;

    if (tid < 64) bts[tid] = Bb[tid] + Th[tid];

    // staging maps
    const int xrow = tid >> 1, xq0 = (tid & 1) * 4;   // X: 4 float4 per thread
    const int wrow = tid >> 2, wq0 = (tid & 3) * 2;   // W: 2 float4 per thread

    float C[8][4];
#pragma unroll
    for (int nt = 0; nt < 8; nt++)
#pragma unroll
        for (int q = 0; q < 4; q++) C[nt][q] = 0.0f;

    // prefetch chunk 0
    float4 xr[4], wr[2];
#pragma unroll
    for (int i = 0; i < 4; i++)
        xr[i] = *(const float4*)(X + (m0 + xrow) * DIN + 4 * (xq0 + i));
#pragma unroll
    for (int i = 0; i < 2; i++)
        wr[i] = *(const float4*)(W + wrow * 144 + 4 * (wq0 + i));

    for (int kc = 0; kc < 4; kc++) {
        // ---- store staged registers (split hi/lo bf16x2) ----
#pragma unroll
        for (int i = 0; i < 4; i++) {
            const uint2 u0 = bf16_split2(xr[i].x, xr[i].y);
            const uint2 u1 = bf16_split2(xr[i].z, xr[i].w);
            *(uint4*)&Xs2[xrow * SROW8 + 2 * (xq0 + i)] =
                make_uint4(u0.x, u0.y, u1.x, u1.y);
        }
#pragma unroll
        for (int i = 0; i < 2; i++) {
            const uint2 u0 = bf16_split2(wr[i].x, wr[i].y);
            const uint2 u1 = bf16_split2(wr[i].z, wr[i].w);
            *(uint4*)&Ws2[wrow * SROW8 + 2 * (wq0 + i)] =
                make_uint4(u0.x, u0.y, u1.x, u1.y);
        }
        __syncthreads();

        // ---- prefetch next chunk ----
        if (kc < 3) {
            const int kb = (kc + 1) * 32;
#pragma unroll
            for (int i = 0; i < 4; i++)
                xr[i] = *(const float4*)(X + (m0 + xrow) * DIN + kb + 4 * (xq0 + i));
#pragma unroll
            for (int i = 0; i < 2; i++)
                wr[i] = *(const float4*)(W + wrow * 144 + kb + 4 * (wq0 + i));
        }

        // ---- compute: 2 ksteps x 8 ntiles x 3 mma ----
#pragma unroll
        for (int ks = 0; ks < 2; ks++) {
            const int kp = ks * 8 + tig;
            const uint2 A0 = Xs2[(rb + g) * SROW8 + kp];
            const uint2 A1 = Xs2[(rb + 8 + g) * SROW8 + kp];
            const uint2 A2 = Xs2[(rb + g) * SROW8 + kp + 4];
            const uint2 A3 = Xs2[(rb + 8 + g) * SROW8 + kp + 4];
#pragma unroll
            for (int nt = 0; nt < 8; nt++) {
                const uint2 B0 = Ws2[(nt * 8 + g) * SROW8 + kp];
                const uint2 B1 = Ws2[(nt * 8 + g) * SROW8 + kp + 4];
                MMA_BF16(C[nt], A0.x, A1.x, A2.x, A3.x, B0.x, B1.x);
                MMA_BF16(C[nt], A0.y, A1.y, A2.y, A3.y, B0.x, B1.x);
                MMA_BF16(C[nt], A0.x, A1.x, A2.x, A3.x, B0.y, B1.y);
            }
        }
        __syncthreads();
    }

    // ---- epilogue ----
    float2 bt2[8];
#pragma unroll
    for (int nt = 0; nt < 8; nt++)
        bt2[nt] = *(const float2*)&bts[nt * 8 + 2 * tig];

    const size_t r0 = m0 + rb + g;
#pragma unroll
    for (int nt = 0; nt < 8; nt++) {
        const int col = nt * 8 + 2 * tig;
        *(float2*)&g_zx[r0 * GN + col] =
            make_float2(C[nt][0] + bt2[nt].x, C[nt][1] + bt2[nt].y);
        *(float2*)&g_zx[(r0 + 8) * GN + col] =
            make_float2(C[nt][2] + bt2[nt].x, C[nt][3] + bt2[nt].y);
    }
}

// ===========================================================================
// Phase 2 (R8 + diet): 16 lanes/element, 4 elements per 64-thread block.
//   h stored PRE-PACKED (h,h) u64 in smem -> 8 LDS.128/step, no PACK2s;
//   packed f32x2 dots; packed accumulator combine; poly activations;
//   radix-4 shfl scan; 4-step batched prefetch.
// ===========================================================================
#define FMA_X2(d, a, b, c) \
    asm("fma.rn.f32x2 %0, %1, %2, %3;" : "=l"(d) : "l"(a), "l"(b), "l"(c))
#define ADD_X2(d, a, b) \
    asm("add.rn.f32x2 %0, %1, %2;" : "=l"(d) : "l"(a), "l"(b))
#define PACK2(d, x, y) \
    asm("mov.b64 %0, {%1, %2};" : "=l"(d) : "f"(x), "f"(y))
#define UNPACK2(x, y, d) \
    asm("mov.b64 {%0, %1}, %2;" : "=f"(x), "=f"(y) : "l"(d))

#define SA1 0.25f
#define SA3 (-2.0833333e-2f)
#define SA5 (2.0833333e-3f)
#define SA7 (-2.1081349e-4f)
#define SA9 (2.1356922e-5f)
__device__ __forceinline__ float sig_poly(float q) {
    const float u = q * q;
    float p = fmaf(SA9, u, SA7);
    p = fmaf(p, u, SA5);
    p = fmaf(p, u, SA3);
    p = fmaf(p, u, SA1);
    return fmaf(p, q, 0.5f);
}
__device__ __forceinline__ float tanh_pade(float x) {
    const float u = x * x;
    const float n = fmaf(u + 105.0f, u, 945.0f);
    const float d = fmaf(fmaf(15.0f, u, 420.0f), u, 945.0f);
    return __fdividef(x * n, d);
}
__device__ __forceinline__ float scanp(float p, int n) {
    float v1 = __shfl_up_sync(0xffffffffu, p, 1, 16);
    float v2 = __shfl_up_sync(0xffffffffu, p, 2, 16);
    float v3 = __shfl_up_sync(0xffffffffu, p, 3, 16);
    float m = ((n >= 1) ? v1 : 1.0f) * ((n >= 2) ? v2 : 1.0f);
    p *= m * ((n >= 3) ? v3 : 1.0f);
    float w1 = __shfl_up_sync(0xffffffffu, p, 4, 16);
    float w2 = __shfl_up_sync(0xffffffffu, p, 8, 16);
    float w3 = __shfl_up_sync(0xffffffffu, p, 12, 16);
    float mm = ((n >= 4) ? w1 : 1.0f) * ((n >= 8) ? w2 : 1.0f);
    return p * (mm * ((n >= 12) ? w3 : 1.0f));
}

__global__ __launch_bounds__(64) void qlstm_p2(
    const float* __restrict__ W, float* __restrict__ out, const int write_final)
{
    __shared__ unsigned long long hs[2][4][16];   // (h,h) packed per qubit

    const int tid = threadIdx.x;
    const int n   = tid & 15;
    const int grp = tid >> 4;
    const int e   = blockIdx.x * 4 + grp;

    // packed recurrent weights: Wab[j] = (W_f, W_i), Wcd[j] = (W_g, W_o)
    unsigned long long Wab[16], Wcd[16];
#pragma unroll
    for (int j = 0; j < 16; j++) {
        const float w0 = W[(size_t)(0 * 16 + n) * 144 + 128 + j];
        const float w1 = W[(size_t)(1 * 16 + n) * 144 + 128 + j];
        const float w2 = W[(size_t)(2 * 16 + n) * 144 + 128 + j];
        const float w3 = W[(size_t)(3 * 16 + n) * 144 + 128 + j];
        PACK2(Wab[j], w0, w1);
        PACK2(Wcd[j], w2, w3);
    }

    float c = 0.0f, h = 0.0f;
    hs[0][grp][n] = 0ULL;
    __syncwarp();

    const size_t SS = (size_t)B_DIM * GN;
    const float* zp = g_zx + (size_t)e * GN + n;
    float* outp = out + (size_t)e * NQ + n;

    float zc[4][4];
#pragma unroll
    for (int s = 0; s < 4; s++)
#pragma unroll
        for (int g = 0; g < 4; g++) zc[s][g] = zp[s * SS + g * 16];
    zp += 4 * SS;

    for (int tb = 0; tb < 64; ++tb) {
        float zn[4][4];
#pragma unroll
        for (int s = 0; s < 4; s++)
#pragma unroll
            for (int g = 0; g < 4; g++) zn[s][g] = zp[s * SS + g * 16];
        zp += 4 * SS;

#pragma unroll
        for (int s = 0; s < 4; s++) {
            const int buf = s & 1;
            unsigned long long hv2[16];
            {
                const ulonglong2* hp = (const ulonglong2*)hs[buf][grp];
#pragma unroll
                for (int q = 0; q < 8; q++) {
                    const ulonglong2 v = hp[q];
                    hv2[2 * q] = v.x;
                    hv2[2 * q + 1] = v.y;
                }
            }
            unsigned long long ab0, ab1, cd0, cd1;
            PACK2(ab0, zc[s][0], zc[s][1]);
            PACK2(cd0, zc[s][2], zc[s][3]);
            PACK2(ab1, 0.0f, 0.0f);
            PACK2(cd1, 0.0f, 0.0f);
#pragma unroll
            for (int j = 0; j < 8; j++) {
                FMA_X2(ab0, hv2[j], Wab[j], ab0);
                FMA_X2(cd0, hv2[j], Wcd[j], cd0);
                FMA_X2(ab1, hv2[j + 8], Wab[j + 8], ab1);
                FMA_X2(cd1, hv2[j + 8], Wcd[j + 8], cd1);
            }
            ADD_X2(ab0, ab0, ab1);
            ADD_X2(cd0, cd0, cd1);
            float za, zb, zg, zo;
            UNPACK2(za, zb, ab0);
            UNPACK2(zg, zo, cd0);

            const float q0 = scanp(__cosf(za), n);
            const float q1 = scanp(__cosf(zb), n);
            const float q2 = scanp(__cosf(zg), n);
            const float q3 = scanp(__cosf(zo), n);

            const float f  = sig_poly(q0);
            const float ii = sig_poly(q1);
            const float gg = tanh_pade(q2);
            const float oo = sig_poly(q3);
            c = fmaf(f, c, ii * gg);
            h = oo * tanh_pade(c);

            outp[0] = h;
            outp += B_DIM * NQ;
            unsigned long long hp2;
            PACK2(hp2, h, h);
            hs[buf ^ 1][grp][n] = hp2;
            __syncwarp();
        }
#pragma unroll
        for (int s = 0; s < 4; s++)
#pragma unroll
            for (int g = 0; g < 4; g++) zc[s][g] = zn[s][g];
    }

    if (write_final) {
        float* hx = out + (size_t)T_DIM * B_DIM * NQ;
        hx[(size_t)e * NQ + n] = h;
        hx[(size_t)B_DIM * NQ + (size_t)e * NQ + n] = c;
    }
}

// ---------------------------------------------------------------------------
extern "C" void kernel_launch(void* const* d_in, const int* in_sizes, int n_in,
                              void* d_out, int out_size) {
    const float* X  = (const float*)d_in[0];
    const float* W  = (const float*)d_in[1];
    const float* Bb = (const float*)d_in[2];
    const float* Th = (const float*)d_in[3];
    float* out = (float*)d_out;

    qlstm_p1<<<M_TOT / 128, 256, P1_SMEM>>>(X, W, Bb, Th);

    const int need = T_DIM * B_DIM * NQ + 2 * B_DIM * NQ;
    const int wf = (out_size >= need) ? 1 : 0;
    qlstm_p2<<<B_DIM / 4, 64>>>(W, out, wf);
}

// round 12
// speedup vs baseline: 1.5918x; 1.2975x over previous
#include <cuda_runtime.h>
#include <cstdint>
#include <cstddef>

#define T_DIM 256
#define B_DIM 2048
#define DIN   128
#define NQ    16
#define GN    64
#define M_TOT (T_DIM * B_DIM)

// ZX scratch padded by 4 timesteps so phase-2 prefetch needs no bounds check.
__device__ __align__(256) float g_zx[(size_t)(T_DIM + 4) * B_DIM * GN];

// ===========================================================================
// Phase 1: ZX = X @ Wx^T + (b+theta) via mma.sync m16n8k16 fp16, 2xFP16:
//   X = Xh + Xl (fp16 limbs, exact to 2^-22), W = fp16(W) single.
//   z = Xh*Wh + Xl*Wh;  dropped X*(W-Wh) ~ 1.6e-4 abs on z.
// Block: 256 thr / 8 warps; warp tile 32 rows x 64 cols; block 256 rows.
// K = 128 in 4 chunks of 32, register-prefetched.
// Xs: (hi,lo) f16x2 pairs per kpair, row stride 20 uint2 (R5 measured layout).
// Wp: fp16x2 pair layout [row][12], slot j=ks*4+tig holds (F(kp),F(kp+4))
//     -> B fragment is ONE LDS.64; stride 12 => banks 24g+2t, conflict-free.
// ===========================================================================
#define SROW8 20
#define WROW  12

__device__ __forceinline__ uint2 f16_split2(float x, float y) {
    uint32_t h, l;
    asm("cvt.rn.f16x2.f32 %0, %1, %2;" : "=r"(h) : "f"(y), "f"(x));
    float hx, hy;
    asm("{\n\t.reg .b16 lo, hi;\n\tmov.b32 {lo, hi}, %2;\n\t"
        "cvt.f32.f16 %0, lo;\n\tcvt.f32.f16 %1, hi;\n\t}"
        : "=f"(hx), "=f"(hy) : "r"(h));
    asm("cvt.rn.f16x2.f32 %0, %1, %2;" : "=r"(l) : "f"(y - hy), "f"(x - hx));
    return make_uint2(h, l);
}
__device__ __forceinline__ uint32_t f16x2_of(float x, float y) {
    uint32_t r;
    asm("cvt.rn.f16x2.f32 %0, %1, %2;" : "=r"(r) : "f"(y), "f"(x));
    return r;
}

#define MMA_FP16(c, a0, a1, a2, a3, b0, b1) \
    asm volatile("mma.sync.aligned.m16n8k16.row.col.f32.f16.f16.f32 " \
        "{%0,%1,%2,%3}, {%4,%5,%6,%7}, {%8,%9}, {%0,%1,%2,%3};" \
        : "+f"((c)[0]), "+f"((c)[1]), "+f"((c)[2]), "+f"((c)[3]) \
        : "r"(a0), "r"(a1), "r"(a2), "r"(a3), "r"(b0), "r"(b1))

__global__ __launch_bounds__(256, 2) void qlstm_p1(
    const float* __restrict__ X,
    const float* __restrict__ W,      // [64][144]
    const float* __restrict__ Bb,
    const float* __restrict__ Th)
{
    __shared__ float bts[64];
    __shared__ uint2 Wp[64 * WROW];     // fp16 pairs, 6 KB
    __shared__ uint2 Xs2[256 * SROW8];  // (hi,lo) pairs, 40 KB

    const int tid  = threadIdx.x;
    const int lane = tid & 31, w = tid >> 5;
    const int g = lane >> 2, tig = lane & 3;
    const int rb = w * 32;
    const size_t m0 = (size_t)blockIdx.x * 256;

    if (tid < 64) bts[tid] = Bb[tid] + Th[tid];

    const int sr = tid >> 3, sq = tid & 7;
    // W store slots for this thread's two kpairs (fixed per thread)
    const int kp0 = 2 * sq, kp1 = 2 * sq + 1;
    const int j0 = ((kp0 >> 3) << 2) | (kp0 & 3), h0 = (kp0 >> 2) & 1;
    const int j1 = ((kp1 >> 3) << 2) | (kp1 & 3), h1 = (kp1 >> 2) & 1;

    float C[2][8][4];
#pragma unroll
    for (int s = 0; s < 2; s++)
#pragma unroll
        for (int nt = 0; nt < 8; nt++)
#pragma unroll
            for (int q = 0; q < 4; q++) C[s][nt][q] = 0.0f;

    // prefetch chunk 0
    float4 xr[8], wr[2];
#pragma unroll
    for (int i = 0; i < 8; i++)
        xr[i] = *(const float4*)(X + (m0 + sr + 32 * i) * DIN + 4 * sq);
#pragma unroll
    for (int i = 0; i < 2; i++)
        wr[i] = *(const float4*)(W + (sr + 32 * i) * 144 + 4 * sq);

    for (int kc = 0; kc < 4; kc++) {
        // ---- stage X (hi/lo split) ----
#pragma unroll
        for (int i = 0; i < 8; i++) {
            const uint2 u0 = f16_split2(xr[i].x, xr[i].y);
            const uint2 u1 = f16_split2(xr[i].z, xr[i].w);
            *(uint4*)&Xs2[(sr + 32 * i) * SROW8 + 2 * sq] =
                make_uint4(u0.x, u0.y, u1.x, u1.y);
        }
        // ---- stage W (single fp16, pair layout) ----
#pragma unroll
        for (int i = 0; i < 2; i++) {
            const int row = sr + 32 * i;
            ((uint32_t*)&Wp[row * WROW + j0])[h0] = f16x2_of(wr[i].x, wr[i].y);
            ((uint32_t*)&Wp[row * WROW + j1])[h1] = f16x2_of(wr[i].z, wr[i].w);
        }
        __syncthreads();

        // ---- prefetch next chunk (overlaps compute) ----
        if (kc < 3) {
            const int kb = (kc + 1) * 32;
#pragma unroll
            for (int i = 0; i < 8; i++)
                xr[i] = *(const float4*)(X + (m0 + sr + 32 * i) * DIN + kb + 4 * sq);
#pragma unroll
            for (int i = 0; i < 2; i++)
                wr[i] = *(const float4*)(W + (sr + 32 * i) * 144 + kb + 4 * sq);
        }

        // ---- compute: 2 ksteps x 8 ntiles x 4 mma ----
#pragma unroll
        for (int ks = 0; ks < 2; ks++) {
            const int kp = ks * 8 + tig;
            const uint2 A0 = Xs2[(rb + g) * SROW8 + kp];
            const uint2 A1 = Xs2[(rb + 8 + g) * SROW8 + kp];
            const uint2 A2 = Xs2[(rb + g) * SROW8 + kp + 4];
            const uint2 A3 = Xs2[(rb + 8 + g) * SROW8 + kp + 4];
            const uint2 D0 = Xs2[(rb + 16 + g) * SROW8 + kp];
            const uint2 D1 = Xs2[(rb + 24 + g) * SROW8 + kp];
            const uint2 D2 = Xs2[(rb + 16 + g) * SROW8 + kp + 4];
            const uint2 D3 = Xs2[(rb + 24 + g) * SROW8 + kp + 4];
            const int bslot = ks * 4 + tig;
#pragma unroll
            for (int nt = 0; nt < 8; nt++) {
                const uint2 Bp = Wp[(nt * 8 + g) * WROW + bslot];
                MMA_FP16(C[0][nt], A0.x, A1.x, A2.x, A3.x, Bp.x, Bp.y);
                MMA_FP16(C[0][nt], A0.y, A1.y, A2.y, A3.y, Bp.x, Bp.y);
                MMA_FP16(C[1][nt], D0.x, D1.x, D2.x, D3.x, Bp.x, Bp.y);
                MMA_FP16(C[1][nt], D0.y, D1.y, D2.y, D3.y, Bp.x, Bp.y);
            }
        }
        __syncthreads();
    }

    // ---- epilogue: add (b+theta), write float2 pairs ----
    float2 bt2[8];
#pragma unroll
    for (int nt = 0; nt < 8; nt++)
        bt2[nt] = *(const float2*)&bts[nt * 8 + 2 * tig];

#pragma unroll
    for (int s = 0; s < 2; s++) {
        const size_t r0 = m0 + rb + 16 * s + g;
#pragma unroll
        for (int nt = 0; nt < 8; nt++) {
            const int col = nt * 8 + 2 * tig;
            *(float2*)&g_zx[r0 * GN + col] =
                make_float2(C[s][nt][0] + bt2[nt].x, C[s][nt][1] + bt2[nt].y);
            *(float2*)&g_zx[(r0 + 8) * GN + col] =
                make_float2(C[s][nt][2] + bt2[nt].x, C[s][nt][3] + bt2[nt].y);
        }
    }
}

// ===========================================================================
// Phase 2 (R8 verbatim, measured 90.98us): 16 lanes/element, 4 elem / 64-thr
// block; smem h double buffer + syncwarp; packed f32x2 dots; poly
// activations; radix-4 shfl scan; 4-step batched prefetch.
// ===========================================================================
#define FMA_X2(d, a, b, c) \
    asm("fma.rn.f32x2 %0, %1, %2, %3;" : "=l"(d) : "l"(a), "l"(b), "l"(c))
#define PACK2(d, x, y) \
    asm("mov.b64 %0, {%1, %2};" : "=l"(d) : "f"(x), "f"(y))
#define UNPACK2(x, y, d) \
    asm("mov.b64 {%0, %1}, %2;" : "=f"(x), "=f"(y) : "l"(d))

#define SA1 0.25f
#define SA3 (-2.0833333e-2f)
#define SA5 (2.0833333e-3f)
#define SA7 (-2.1081349e-4f)
#define SA9 (2.1356922e-5f)
__device__ __forceinline__ float sig_poly(float q) {
    const float u = q * q;
    float p = fmaf(SA9, u, SA7);
    p = fmaf(p, u, SA5);
    p = fmaf(p, u, SA3);
    p = fmaf(p, u, SA1);
    return fmaf(p, q, 0.5f);
}
__device__ __forceinline__ float tanh_pade(float x) {
    const float u = x * x;
    const float n = fmaf(u + 105.0f, u, 945.0f);
    const float d = fmaf(fmaf(15.0f, u, 420.0f), u, 945.0f);
    return __fdividef(x * n, d);
}
__device__ __forceinline__ float scanp(float p, int n) {
    float v1 = __shfl_up_sync(0xffffffffu, p, 1, 16);
    float v2 = __shfl_up_sync(0xffffffffu, p, 2, 16);
    float v3 = __shfl_up_sync(0xffffffffu, p, 3, 16);
    float m = ((n >= 1) ? v1 : 1.0f) * ((n >= 2) ? v2 : 1.0f);
    p *= m * ((n >= 3) ? v3 : 1.0f);
    float w1 = __shfl_up_sync(0xffffffffu, p, 4, 16);
    float w2 = __shfl_up_sync(0xffffffffu, p, 8, 16);
    float w3 = __shfl_up_sync(0xffffffffu, p, 12, 16);
    float mm = ((n >= 4) ? w1 : 1.0f) * ((n >= 8) ? w2 : 1.0f);
    return p * (mm * ((n >= 12) ? w3 : 1.0f));
}

__global__ __launch_bounds__(64) void qlstm_p2(
    const float* __restrict__ W, float* __restrict__ out, const int write_final)
{
    __shared__ float hs[2][4][16];

    const int tid = threadIdx.x;
    const int n   = tid & 15;
    const int grp = tid >> 4;
    const int e   = blockIdx.x * 4 + grp;

    unsigned long long Wab[16], Wcd[16];
#pragma unroll
    for (int j = 0; j < 16; j++) {
        const float w0 = W[(size_t)(0 * 16 + n) * 144 + 128 + j];
        const float w1 = W[(size_t)(1 * 16 + n) * 144 + 128 + j];
        const float w2 = W[(size_t)(2 * 16 + n) * 144 + 128 + j];
        const float w3 = W[(size_t)(3 * 16 + n) * 144 + 128 + j];
        PACK2(Wab[j], w0, w1);
        PACK2(Wcd[j], w2, w3);
    }

    float c = 0.0f, h = 0.0f;
    hs[0][grp][n] = 0.0f;
    __syncwarp();

    const size_t SS = (size_t)B_DIM * GN;
    const float* zp = g_zx + (size_t)e * GN + n;
    float* outp = out + (size_t)e * NQ + n;

    float zc[4][4];
#pragma unroll
    for (int s = 0; s < 4; s++)
#pragma unroll
        for (int g = 0; g < 4; g++) zc[s][g] = zp[s * SS + g * 16];
    zp += 4 * SS;

    for (int tb = 0; tb < 64; ++tb) {
        float zn[4][4];
#pragma unroll
        for (int s = 0; s < 4; s++)
#pragma unroll
            for (int g = 0; g < 4; g++) zn[s][g] = zp[s * SS + g * 16];
        zp += 4 * SS;

#pragma unroll
        for (int s = 0; s < 4; s++) {
            const int buf = s & 1;
            float hv[16];
            {
                const float4* hp = (const float4*)hs[buf][grp];
#pragma unroll
                for (int q = 0; q < 4; q++) {
                    const float4 v = hp[q];
                    hv[4 * q + 0] = v.x; hv[4 * q + 1] = v.y;
                    hv[4 * q + 2] = v.z; hv[4 * q + 3] = v.w;
                }
            }
            unsigned long long ab0, ab1, cd0, cd1;
            PACK2(ab0, zc[s][0], zc[s][1]);
            PACK2(cd0, zc[s][2], zc[s][3]);
            PACK2(ab1, 0.0f, 0.0f);
            PACK2(cd1, 0.0f, 0.0f);
#pragma unroll
            for (int j = 0; j < 8; j++) {
                unsigned long long h20, h21;
                PACK2(h20, hv[j], hv[j]);
                PACK2(h21, hv[j + 8], hv[j + 8]);
                FMA_X2(ab0, h20, Wab[j], ab0);
                FMA_X2(cd0, h20, Wcd[j], cd0);
                FMA_X2(ab1, h21, Wab[j + 8], ab1);
                FMA_X2(cd1, h21, Wcd[j + 8], cd1);
            }
            float za, zb, zg, zo, t0, t1;
            UNPACK2(za, zb, ab0); UNPACK2(t0, t1, ab1);
            za += t0; zb += t1;
            UNPACK2(zg, zo, cd0); UNPACK2(t0, t1, cd1);
            zg += t0; zo += t1;

            const float q0 = scanp(__cosf(za), n);
            const float q1 = scanp(__cosf(zb), n);
            const float q2 = scanp(__cosf(zg), n);
            const float q3 = scanp(__cosf(zo), n);

            const float f  = sig_poly(q0);
            const float ii = sig_poly(q1);
            const float gg = tanh_pade(q2);
            const float oo = sig_poly(q3);
            c = fmaf(f, c, ii * gg);
            h = oo * tanh_pade(c);

            outp[0] = h;
            outp += B_DIM * NQ;
            hs[buf ^ 1][grp][n] = h;
            __syncwarp();
        }
#pragma unroll
        for (int s = 0; s < 4; s++)
#pragma unroll
            for (int g = 0; g < 4; g++) zc[s][g] = zn[s][g];
    }

    if (write_final) {
        float* hx = out + (size_t)T_DIM * B_DIM * NQ;
        hx[(size_t)e * NQ + n] = h;
        hx[(size_t)B_DIM * NQ + (size_t)e * NQ + n] = c;
    }
}

// ---------------------------------------------------------------------------
extern "C" void kernel_launch(void* const* d_in, const int* in_sizes, int n_in,
                              void* d_out, int out_size) {
    const float* X  = (const float*)d_in[0];
    const float* W  = (const float*)d_in[1];
    const float* Bb = (const float*)d_in[2];
    const float* Th = (const float*)d_in[3];
    float* out = (float*)d_out;

    qlstm_p1<<<M_TOT / 256, 256>>>(X, W, Bb, Th);

    const int need = T_DIM * B_DIM * NQ + 2 * B_DIM * NQ;
    const int wf = (out_size >= need) ? 1 : 0;
    qlstm_p2<<<B_DIM / 4, 64>>>(W, out, wf);
}